// round 10
// baseline (speedup 1.0000x reference)
#include <cuda_runtime.h>
#include <cuda_bf16.h>
#include <cstdint>

#define NN 193536
#define BB 16
#define CC 9
#define KK 1000
#define BC 144            // BB*CC
#define MAXDET 100
#define SCORE_T 0.05f
#define IOU_T 0.5f
#define CAP 4096          // per-(b,c) candidate buffer capacity

// keys are positive floats in (0.05, 1): 20-bit prefixes span [0x3D4CC, 0x3F7FF]
#define P_LO 0x3D4CCu
#define HB 9012
#define HBPAD 9024        // padded to 282*32
#define KT_MIN 0x3D4CCCCEu   // smallest uint key with float > 0.05f

// ---------------- scratch (static device globals; no dynamic alloc) ----------------
__device__ unsigned           g_T[BC];
__device__ int                g_ccount[BC];
__device__ unsigned long long g_cand[(size_t)BC * CAP];   // 4.7 MB candidate buffers
__device__ float              g_topval[BC * KK];
__device__ float4             g_topbox[BC * KK];
__device__ unsigned           g_mask32[(size_t)BC * KK * 32];  // 18.4 MB suppression bitmatrix
__device__ float              g_val[BC * KK];              // post-NMS score (0 for invalid)
__device__ float              g_cval[BC * KK];             // compacted survivors (desc order)
__device__ int                g_cidx[BC * KK];
__device__ int                g_cnt[BC];

__device__ __forceinline__ float sigx(float x) { return 1.0f / (1.0f + expf(-x)); }

__device__ __forceinline__ float get_score(const float* cls, const float* obj,
                                           int b, int c, int n) {
    float x = cls[((size_t)b * NN + n) * CC + c];
    float y = obj[(size_t)b * NN + n];
    return sigx(x) * sigx(y);
}

// ---------------- K0: per-(b,c) sample threshold + counter reset ----------------
__global__ __launch_bounds__(1024) void sample_kernel(const float* __restrict__ cls,
                                                      const float* __restrict__ obj) {
    int bc = blockIdx.x, b = bc / CC, c = bc % CC;
    int tid = threadIdx.x;
    __shared__ unsigned samp[4096];
    if (tid == 0) g_ccount[bc] = 0;
    for (int i = tid; i < 4096; i += 1024) {
        int n = i * 47;                       // 47*4095 = 192465 < NN
        float s = get_score(cls, obj, b, c, n);
        samp[i] = (s > SCORE_T) ? __float_as_uint(s) : 0u;
    }
    __syncthreads();
    for (int k = 2; k <= 4096; k <<= 1)
        for (int j = k >> 1; j > 0; j >>= 1) {
            __syncthreads();
            for (int i = tid; i < 4096; i += 1024) {
                int ixj = i ^ j;
                if (ixj > i) {
                    unsigned a = samp[i], bv = samp[ixj];
                    if (((i & k) == 0) ? (a < bv) : (a > bv)) { samp[i] = bv; samp[ixj] = a; }
                }
            }
        }
    __syncthreads();
    if (tid == 0) {
        unsigned t = samp[58];                // 59th largest sample (expected pop rank ~2513)
        g_T[bc] = (t > KT_MIN) ? t : KT_MIN;
    }
}

// ---------------- K1: fused sigmoid + candidate gather (no g_scores!) ----------------
__global__ __launch_bounds__(256) void gather_kernel(const float* __restrict__ cls,
                                                     const float* __restrict__ obj) {
    int b = blockIdx.y;
    int n0 = blockIdx.x * 256;
    int tid = threadIdx.x;
    __shared__ float sh[2304];
    __shared__ unsigned Ts[CC];
    const float* src = cls + ((size_t)b * NN + n0) * CC;
    for (int i = tid; i < 2304; i += 256) sh[i] = src[i];
    if (tid < CC) Ts[tid] = g_T[b * CC + tid];
    __syncthreads();
    int n = n0 + tid;
    float so = sigx(obj[(size_t)b * NN + n]);
#pragma unroll
    for (int c = 0; c < CC; c++) {
        float s = sigx(sh[tid * CC + c]) * so;
        unsigned k = __float_as_uint(s);
        if (s > SCORE_T && k >= Ts[c]) {
            int bc = b * CC + c;
            int p = atomicAdd(&g_ccount[bc], 1);
            if (p < CAP)
                g_cand[(size_t)bc * CAP + p] =
                    ((unsigned long long)k << 32) |
                    (unsigned long long)(0xFFFFFFFFu - (unsigned)n);
        }
    }
}

// ---------------- scan helper: boundary bin from top, given remaining need ----------------
__device__ __forceinline__ void scan_boundary(unsigned* hist, unsigned* gsum, int NG,
                                              int tid, int* sh_sel, int* sh_need,
                                              int* sh_take, unsigned* sh_gat) {
    if (tid < NG) {
        unsigned t = 0;
        int base = tid * 32;
#pragma unroll 8
        for (int i = 0; i < 32; i++) t += hist[base + i];
        gsum[tid] = t;
    }
    __syncthreads();
    if (tid == 0) {
        int need = *sh_need;
        unsigned acc = 0;
        int g = NG - 1;
        for (; g >= 0; g--) {
            if (acc + gsum[g] >= (unsigned)need) break;
            acc += gsum[g];
        }
        if (g < 0) {
            *sh_take = 1;
        } else {
            int bin = g * 32 + 31;
            for (;; bin--) {
                if (acc + hist[bin] >= (unsigned)need) break;
                acc += hist[bin];
            }
            *sh_sel = bin;
            *sh_need = need - (int)acc;
            *sh_gat = acc + hist[bin];
        }
    }
    __syncthreads();
}

__device__ __forceinline__ void hist_add(unsigned* hist, int bin) {
    unsigned m = __match_any_sync(__activemask(), bin);
    int leader = __ffs(m) - 1;
    if ((threadIdx.x & 31) == leader) atomicAdd(&hist[bin], __popc(m));
}

// ---------------- K2: per-(b,c) exact top-1000 from candidate buffer + decode ----------------
__global__ __launch_bounds__(1024) void select_kernel(const float* __restrict__ cls,
                                                      const float* __restrict__ obj,
                                                      const float4* __restrict__ anchors,
                                                      const float4* __restrict__ deltas) {
    int bc = blockIdx.x;
    int b = bc / CC, c = bc % CC;
    int tid = threadIdx.x;

    __shared__ __align__(16) unsigned char sraw[HBPAD * 4];   // 36 KB overlay
    unsigned* hist = (unsigned*)sraw;
    unsigned long long* arr = (unsigned long long*)sraw;      // 32 KB, overlays hist
    __shared__ unsigned gsum[288];
    __shared__ int sh_sel, sh_need, sh_take, sh_cnt;
    __shared__ unsigned sh_gat;

    int cnt = g_ccount[bc];
    unsigned T = g_T[bc];
    bool fast = (cnt <= CAP) && (cnt >= KK || T == KT_MIN);

    if (fast) {
        // ---- fast path: candidates already in global buffer ----
        for (int i = tid; i < CAP; i += 1024)
            arr[i] = (i < cnt) ? g_cand[(size_t)bc * CAP + i] : 0ull;
        __syncthreads();
    } else {
        // ---- exact fallback (cold): recompute scores strided, full radix-select ----
        for (int i = tid; i < HBPAD; i += 1024) hist[i] = 0;
        if (tid == 0) { sh_need = KK; sh_take = 0; }
        __syncthreads();
        for (int n = tid; n < NN; n += 1024) {
            float s = get_score(cls, obj, b, c, n);
            if (s > SCORE_T) {
                int bin = (int)(__float_as_uint(s) >> 12) - (int)P_LO;
                bin = min(max(bin, 0), HB - 1);
                hist_add(hist, bin);
            }
        }
        __syncthreads();
        scan_boundary(hist, gsum, 282, tid, &sh_sel, &sh_need, &sh_take, &sh_gat);
        unsigned Kt;
        if (sh_take) {
            Kt = KT_MIN;
        } else {
            unsigned prefix = P_LO + (unsigned)sh_sel;
            Kt = prefix << 12;
            if (sh_gat > 2048u) {
                __syncthreads();
                for (int i = tid; i < 4096; i += 1024) hist[i] = 0;
                __syncthreads();
                for (int n = tid; n < NN; n += 1024) {
                    float s = get_score(cls, obj, b, c, n);
                    if (s > SCORE_T) {
                        unsigned k = __float_as_uint(s);
                        if ((k >> 12) == prefix) hist_add(hist, (int)(k & 0xFFF));
                    }
                }
                __syncthreads();
                scan_boundary(hist, gsum, 128, tid, &sh_sel, &sh_need, &sh_take, &sh_gat);
                Kt = (prefix << 12) | (unsigned)sh_sel;
            }
        }
        __syncthreads();
        for (int i = tid; i < CAP; i += 1024) arr[i] = 0ull;
        if (tid == 0) sh_cnt = 0;
        __syncthreads();
        for (int n = tid; n < NN; n += 1024) {
            float s = get_score(cls, obj, b, c, n);
            if (s > SCORE_T) {
                unsigned k = __float_as_uint(s);
                if (k >= Kt) {
                    int p = atomicAdd(&sh_cnt, 1);
                    if (p < CAP)
                        arr[p] = ((unsigned long long)k << 32) |
                                 (unsigned long long)(0xFFFFFFFFu - (unsigned)n);
                }
            }
        }
        __syncthreads();
    }

    // ---- bitonic sort 4096 desc (score desc, idx asc on ties) ----
    for (int k = 2; k <= 4096; k <<= 1)
        for (int j = k >> 1; j > 0; j >>= 1) {
            __syncthreads();
            for (int i = tid; i < 4096; i += 1024) {
                int ixj = i ^ j;
                if (ixj > i) {
                    unsigned long long a = arr[i], bv = arr[ixj];
                    if (((i & k) == 0) ? (a < bv) : (a > bv)) { arr[i] = bv; arr[ixj] = a; }
                }
            }
        }
    __syncthreads();

    // ---- epilogue: write topval + decode box inline ----
    if (tid < KK) {
        unsigned long long v = arr[tid];
        float val;
        int idx;
        if (v) {
            val = __uint_as_float((unsigned)(v >> 32));
            idx = (int)(0xFFFFFFFFu - (unsigned)v);
        } else {
            val = -1.0f;    // padding; cannot surface in output
            idx = tid;
        }
        g_topval[bc * KK + tid] = val;
        float4 an = anchors[idx];
        float4 dl = deltas[(size_t)b * NN + idx];
        float acx = (an.x + an.z) * 0.5f, acy = (an.y + an.w) * 0.5f;
        float aw = fmaxf(an.z - an.x, 1.0f), ah = fmaxf(an.w - an.y, 1.0f);
        float cx = dl.x * aw + acx, cy = dl.y * ah + acy;
        float w = expf(fminf(dl.z, 4.0f)) * aw;
        float h = expf(fminf(dl.w, 4.0f)) * ah;
        g_topbox[bc * KK + tid] = make_float4(cx - w * 0.5f, cy - h * 0.5f,
                                              cx + w * 0.5f, cy + h * 0.5f);
    }
}

// ---------------- K3: NMS suppression bitmatrix (row-pair per warp, u32 words) ----------------
__global__ __launch_bounds__(1024) void nms_mask_kernel() {
    int bc = blockIdx.x;
    int tid = threadIdx.x;
    int lane = tid & 31;
    int wid = tid >> 5;
    __shared__ float4 sb[KK];
    __shared__ float sa[KK];
    for (int i = tid; i < KK; i += 1024) {
        float4 bx = g_topbox[bc * KK + i];
        sb[i] = bx;
        sa[i] = (bx.z - bx.x) * (bx.w - bx.y);
    }
    __syncthreads();
    int gw = blockIdx.y * 32 + wid;   // 0..127 global warp within bc
    for (int p = gw; p < KK / 2; p += 128) {
        int i0 = p * 2, i1 = i0 + 1;
        float4 bA = sb[i0], bB = sb[i1];
        float aA = sa[i0], aB = sa[i1];
        unsigned* r0 = &g_mask32[((size_t)bc * KK + i0) * 32];
        unsigned* r1 = r0 + 32;
        for (int w = i0 >> 5; w < 32; w++) {
            int j = (w << 5) + lane;
            bool sA = false, sB = false;
            if (j < KK) {
                float4 bj = sb[j];
                float aj = sa[j];
                float x1a = fmaxf(bA.x, bj.x), y1a = fmaxf(bA.y, bj.y);
                float x2a = fminf(bA.z, bj.z), y2a = fminf(bA.w, bj.w);
                float ia = fmaxf(x2a - x1a, 0.0f) * fmaxf(y2a - y1a, 0.0f);
                sA = (j > i0) && (ia > 0.5f * fmaxf(aA + aj - ia, 1e-6f));
                float x1b = fmaxf(bB.x, bj.x), y1b = fmaxf(bB.y, bj.y);
                float x2b = fminf(bB.z, bj.z), y2b = fminf(bB.w, bj.w);
                float ib = fmaxf(x2b - x1b, 0.0f) * fmaxf(y2b - y1b, 0.0f);
                sB = (j > i1) && (ib > 0.5f * fmaxf(aB + aj - ib, 1e-6f));
            }
            unsigned balA = __ballot_sync(0xFFFFFFFFu, sA);
            unsigned balB = __ballot_sync(0xFFFFFFFFu, sB);
            if (lane == 0) { r0[w] = balA; r1[w] = balB; }
        }
    }
}

// ---------------- K4: greedy reduction, 32x32 chunk solve + cp.async staging ----------------
__device__ __forceinline__ void cp_async16(unsigned saddr, const void* gaddr) {
    asm volatile("cp.async.cg.shared.global [%0], [%1], 16;" :: "r"(saddr), "l"(gaddr));
}
__device__ __forceinline__ void cp_commit() { asm volatile("cp.async.commit_group;"); }
__device__ __forceinline__ void cp_wait1() { asm volatile("cp.async.wait_group 1;"); }

__global__ __launch_bounds__(32) void nms_reduce_kernel() {
    int bc = blockIdx.x;
    int lane = threadIdx.x;
    const unsigned* m32 = g_mask32 + (size_t)bc * KK * 32;
    __shared__ __align__(16) unsigned stage[2][1024];   // 8 KB double buffer

    unsigned sbase0 = (unsigned)__cvta_generic_to_shared(&stage[0][0]);
    unsigned sbase1 = (unsigned)__cvta_generic_to_shared(&stage[1][0]);

    // issue chunk c into the given stage buffer.
    // chunk = nrows rows x 128 B/row; per lane: nrows*128/(32*16) = nrows/4 ops of 16 B.
    auto issue = [&](int c, unsigned sbase) {
        int nrows = min(32, KK - c * 32);
        int nops = nrows / 4;
        const char* g = (const char*)(m32 + (size_t)c * 1024);
        for (int k = 0; k < nops; k++) {
            int off = (k * 32 + lane) * 16;
            cp_async16(sbase + off, g + off);
        }
    };

    issue(0, sbase0);
    cp_commit();

    unsigned removed = 0u;
    unsigned keepbits = 0u;
    for (int c = 0; c < 32; c++) {
        if (c < 31) issue(c + 1, (c & 1) ? sbase0 : sbase1);
        cp_commit();
        cp_wait1();
        __syncwarp();
        const unsigned* st = stage[c & 1];
        int nr = (c == 31) ? 8 : 32;
        unsigned w[32];
#pragma unroll
        for (int s = 0; s < 32; s++) w[s] = (s < nr) ? st[s * 32 + lane] : 0u;
        // resolve greedy within chunk (lane c's column is the diagonal)
        unsigned kb = ~removed;
        if (c == 31) kb &= 0xFFu;
#pragma unroll
        for (int s = 0; s < 32; s++) {
            unsigned m = (unsigned)(-(int)((kb >> s) & 1u));
            kb &= ~(w[s] & m);
        }
        kb = __shfl_sync(0xFFFFFFFFu, kb, c);
        // apply kept rows' suppression (4-way OR trees)
        unsigned a0 = 0, a1 = 0, a2 = 0, a3 = 0;
#pragma unroll
        for (int s = 0; s < 32; s += 4) {
            a0 |= w[s + 0] & (unsigned)(-(int)((kb >> (s + 0)) & 1u));
            a1 |= w[s + 1] & (unsigned)(-(int)((kb >> (s + 1)) & 1u));
            a2 |= w[s + 2] & (unsigned)(-(int)((kb >> (s + 2)) & 1u));
            a3 |= w[s + 3] & (unsigned)(-(int)((kb >> (s + 3)) & 1u));
        }
        removed |= (a0 | a1) | (a2 | a3);
        if (lane == c) keepbits = kb;
        __syncwarp();
    }

    // ---- parallel epilogue: apply score threshold, write g_val, compact survivors ----
    int cnt = 0;
    for (int w = 0; w < 32; w++) {
        unsigned kb = __shfl_sync(0xFFFFFFFFu, keepbits, w);
        int i = w * 32 + lane;
        float v = (i < KK) ? g_topval[bc * KK + i] : -1.0f;
        bool valid = (i < KK) && ((kb >> lane) & 1u) && (v > SCORE_T);
        if (i < KK) g_val[bc * KK + i] = valid ? v : 0.0f;
        unsigned bal = __ballot_sync(0xFFFFFFFFu, valid);
        int pos = cnt + __popc(bal & ((1u << lane) - 1u));
        if (valid) {
            g_cval[bc * KK + pos] = v;      // survivors stay score-descending
            g_cidx[bc * KK + pos] = i;
        }
        cnt += __popc(bal);
    }
    if (lane == 0) g_cnt[bc] = cnt;
}

// ---------------- K5: per-image top-100 over 9 classes ----------------
__global__ __launch_bounds__(512) void final_kernel(float* __restrict__ out) {
    int b = blockIdx.x;
    int tid = threadIdx.x;
    __shared__ unsigned long long arr[1024];
    for (int i = tid; i < 1024; i += 512) arr[i] = 0ull;
    __syncthreads();
    for (int s = tid; s < 900; s += 512) {
        int c = s / 100, r = s % 100;
        int bc = b * 9 + c;
        if (r < g_cnt[bc]) {
            float v = g_cval[bc * KK + r];
            int k = g_cidx[bc * KK + r];
            unsigned flat = (unsigned)(c * KK + k);
            arr[s] = ((unsigned long long)__float_as_uint(v) << 32) |
                     (unsigned long long)(0xFFFFFFFFu - flat);
        }
    }
    __syncthreads();
    for (int k = 2; k <= 1024; k <<= 1)
        for (int j = k >> 1; j > 0; j >>= 1) {
            __syncthreads();
            for (int i = tid; i < 1024; i += 512) {
                int ixj = i ^ j;
                if (ixj > i) {
                    unsigned long long a = arr[i], bv = arr[ixj];
                    if (((i & k) == 0) ? (a < bv) : (a > bv)) { arr[i] = bv; arr[ixj] = a; }
                }
            }
        }
    __syncthreads();

    float* o = out + (size_t)b * MAXDET * 6;
    if (tid < MAXDET) {
        unsigned long long v = arr[tid];
        if (v) {
            unsigned flat = 0xFFFFFFFFu - (unsigned)v;
            int c = flat / KK, k2 = flat % KK;
            float4 bx = g_topbox[(b * 9 + c) * KK + k2];
            float scv = __uint_as_float((unsigned)(v >> 32));
            o[tid * 6 + 0] = bx.x; o[tid * 6 + 1] = bx.y;
            o[tid * 6 + 2] = bx.z; o[tid * 6 + 3] = bx.w;
            o[tid * 6 + 4] = scv;  o[tid * 6 + 5] = (float)c;
        }
    }
    __syncthreads();
    // exact-tie fallback: < 100 positive detections -> zero-score entries by ascending flat idx
    if (tid == 0 && arr[MAXDET - 1] == 0ull) {
        int f = 0;
        for (int t = 0; t < MAXDET; t++) {
            if (arr[t]) continue;
            while (f < 9000 && g_val[(size_t)b * 9000 + f] != 0.0f) f++;
            int c = 0, k2 = 0;
            float4 bx = make_float4(0.f, 0.f, 0.f, 0.f);
            if (f < 9000) {
                c = f / KK; k2 = f % KK;
                bx = g_topbox[(b * 9 + c) * KK + k2];
                f++;
            }
            o[t * 6 + 0] = bx.x; o[t * 6 + 1] = bx.y;
            o[t * 6 + 2] = bx.z; o[t * 6 + 3] = bx.w;
            o[t * 6 + 4] = 0.0f; o[t * 6 + 5] = (float)c;
        }
    }
}

// ---------------- launch ----------------
extern "C" void kernel_launch(void* const* d_in, const int* in_sizes, int n_in,
                              void* d_out, int out_size) {
    (void)in_sizes; (void)n_in; (void)out_size;
    const float* anchors = (const float*)d_in[0];
    const float* deltas  = (const float*)d_in[1];
    const float* cls     = (const float*)d_in[2];
    const float* obj     = (const float*)d_in[3];
    float* out = (float*)d_out;

    sample_kernel<<<BC, 1024>>>(cls, obj);
    gather_kernel<<<dim3(NN / 256, BB), 256>>>(cls, obj);
    select_kernel<<<BC, 1024>>>(cls, obj, (const float4*)anchors, (const float4*)deltas);
    nms_mask_kernel<<<dim3(BC, 4), 1024>>>();
    nms_reduce_kernel<<<BC, 32>>>();
    final_kernel<<<BB, 512>>>(out);
}

// round 11
// speedup vs baseline: 1.0103x; 1.0103x over previous
#include <cuda_runtime.h>
#include <cuda_bf16.h>
#include <cstdint>

#define NN 193536
#define BB 16
#define CC 9
#define KK 1000
#define BC 144            // BB*CC
#define MAXDET 100
#define SCORE_T 0.05f
#define IOU_T 0.5f

// keys are positive floats in (0.05, 1): 20-bit prefixes span [0x3D4CC, 0x3F7FF]
#define P_LO 0x3D4CCu
#define HB 9012
#define HBPAD 9024        // padded to 282*32
#define KT_MIN 0x3D4CCCCEu   // smallest uint key with float > 0.05f

// ---------------- scratch (static device globals; no dynamic alloc) ----------------
__device__ float    g_scores[(size_t)BC * NN];       // ~111.5 MB, [(b*9+c)][n]
__device__ float    g_topval[BC * KK];
__device__ float4   g_topbox[BC * KK];
__device__ unsigned g_mask32[(size_t)BC * KK * 32];  // 18.4 MB suppression bitmatrix (u32 words)
__device__ float    g_val[BC * KK];                  // post-NMS score (0 for invalid)
__device__ float    g_cval[BC * KK];                 // compacted survivors (desc order)
__device__ int      g_cidx[BC * KK];
__device__ int      g_cnt[BC];

// ---------------- K1: sigmoid + transpose scores to class-major ----------------
__global__ __launch_bounds__(256) void score_kernel(const float* __restrict__ cls,
                                                    const float* __restrict__ obj) {
    int b = blockIdx.y;
    int n0 = blockIdx.x * 256;
    int tid = threadIdx.x;
    __shared__ float sh[256 * 9];
    const float* src = cls + ((size_t)b * NN + n0) * 9;
    for (int i = tid; i < 2304; i += 256) sh[i] = src[i];
    __syncthreads();
    int n = n0 + tid;
    float so = 1.0f / (1.0f + expf(-obj[(size_t)b * NN + n]));
#pragma unroll
    for (int c = 0; c < 9; c++) {
        float s = 1.0f / (1.0f + expf(-sh[tid * 9 + c]));
        g_scores[((size_t)(b * 9 + c)) * NN + n] = s * so;
    }
}

// ---------------- scan helper: boundary bin from top, given remaining need ----------------
__device__ __forceinline__ void scan_boundary(unsigned* hist, unsigned* gsum, int NG,
                                              int tid, int* sh_sel, int* sh_need,
                                              int* sh_take, unsigned* sh_gat) {
    if (tid < NG) {
        unsigned t = 0;
        int base = tid * 32;
#pragma unroll 8
        for (int i = 0; i < 32; i++) t += hist[base + i];
        gsum[tid] = t;
    }
    __syncthreads();
    if (tid == 0) {
        int need = *sh_need;
        unsigned acc = 0;
        int g = NG - 1;
        for (; g >= 0; g--) {
            if (acc + gsum[g] >= (unsigned)need) break;
            acc += gsum[g];
        }
        if (g < 0) {
            *sh_take = 1;  // fewer than `need` candidates total
        } else {
            int bin = g * 32 + 31;
            for (;; bin--) {
                if (acc + hist[bin] >= (unsigned)need) break;
                acc += hist[bin];
            }
            *sh_sel = bin;
            *sh_need = need - (int)acc;          // remaining need inside boundary bin
            *sh_gat = acc + hist[bin];           // total items with key >= bin prefix
        }
    }
    __syncthreads();
}

// ---------------- K2: per-(b,c) exact top-1000 (sample-guided hist) + decode ----------------
__global__ __launch_bounds__(1024) void select_kernel(const float4* __restrict__ anchors,
                                                      const float4* __restrict__ deltas) {
    int bc = blockIdx.x;
    int tid = threadIdx.x;
    const float* sc = g_scores + (size_t)bc * NN;
    const float4* sc4 = (const float4*)sc;

    __shared__ __align__(16) unsigned char sraw[HBPAD * 4];   // 36 KB overlay
    unsigned* hist = (unsigned*)sraw;
    unsigned* samp = (unsigned*)sraw;                         // 8 KB sample buffer
    unsigned long long* arr = (unsigned long long*)sraw;      // 16 KB gather/sort buffer
    __shared__ unsigned gsum[288];
    __shared__ int sh_sel, sh_need, sh_take, sh_cnt;
    __shared__ unsigned sh_gat, sh_T;

    // ---- phase 0: sample 2048 values, sort desc, take 32nd as conservative threshold ----
    for (int i = tid; i < 2048; i += 1024) {
        float s = sc[i * 94];
        samp[i] = (s > SCORE_T) ? __float_as_uint(s) : 0u;
    }
    __syncthreads();
    for (int k = 2; k <= 2048; k <<= 1)
        for (int j = k >> 1; j > 0; j >>= 1) {
            __syncthreads();
            for (int i = tid; i < 2048; i += 1024) {
                int ixj = i ^ j;
                if (ixj > i) {
                    unsigned a = samp[i], b = samp[ixj];
                    if (((i & k) == 0) ? (a < b) : (a > b)) { samp[i] = b; samp[ixj] = a; }
                }
            }
        }
    __syncthreads();
    if (tid == 0) {
        unsigned t = samp[31];                 // 32nd largest sample (expected full rank ~3000)
        sh_T = (t >= KT_MIN) ? t : KT_MIN;
    }
    __syncthreads();
    unsigned T = sh_T;

    // ---- phase 1: histogram over 20-bit prefixes, only keys >= T (few atomics) ----
    for (int attempt = 0; attempt < 2; attempt++) {
        __syncthreads();
        for (int i = tid; i < HBPAD; i += 1024) hist[i] = 0;
        if (tid == 0) { sh_need = KK; sh_take = 0; }
        __syncthreads();
        for (int n4 = tid; n4 < NN / 4; n4 += 1024) {
            float4 v = sc4[n4];
            float sv[4] = {v.x, v.y, v.z, v.w};
#pragma unroll
            for (int c = 0; c < 4; c++) {
                float s = sv[c];
                if (s > SCORE_T) {
                    unsigned k = __float_as_uint(s);
                    if (k >= T) {
                        int bin = (int)(k >> 12) - (int)P_LO;
                        bin = min(max(bin, 0), HB - 1);
                        atomicAdd(&hist[bin], 1u);
                    }
                }
            }
        }
        __syncthreads();
        scan_boundary(hist, gsum, 282, tid, &sh_sel, &sh_need, &sh_take, &sh_gat);
        if (!sh_take || T == KT_MIN) break;    // success, or genuinely <1000 total
        T = KT_MIN;                            // sample threshold too high: full rehist
    }

    unsigned Kt;
    if (sh_take) {
        Kt = KT_MIN;                           // fewer than 1000 total: take everything > thresh
    } else {
        unsigned prefix = P_LO + (unsigned)sh_sel;
        unsigned binlo = prefix << 12;
        Kt = (binlo < T) ? T : binlo;          // boundary bin may be T's own bin
        if (sh_gat > 2048u) {
            // ---- rare refinement: low 12 bits within boundary prefix (exact key bins) ----
            __syncthreads();
            for (int i = tid; i < 4096; i += 1024) hist[i] = 0;
            __syncthreads();
            for (int n4 = tid; n4 < NN / 4; n4 += 1024) {
                float4 v = sc4[n4];
                float sv[4] = {v.x, v.y, v.z, v.w};
#pragma unroll
                for (int c = 0; c < 4; c++) {
                    float s = sv[c];
                    if (s > SCORE_T) {
                        unsigned k = __float_as_uint(s);
                        if (k >= T && (k >> 12) == prefix) atomicAdd(&hist[k & 0xFFF], 1u);
                    }
                }
            }
            __syncthreads();
            scan_boundary(hist, gsum, 128, tid, &sh_sel, &sh_need, &sh_take, &sh_gat);
            Kt = (prefix << 12) | (unsigned)sh_sel;   // exact 32-bit threshold (>= T)
        }
    }

    // ---- phase 2: gather candidates with key >= Kt ----
    __syncthreads();
    for (int i = tid; i < 2048; i += 1024) arr[i] = 0ull;
    if (tid == 0) sh_cnt = 0;
    __syncthreads();
    for (int n4 = tid; n4 < NN / 4; n4 += 1024) {
        float4 v = sc4[n4];
        float sv[4] = {v.x, v.y, v.z, v.w};
#pragma unroll
        for (int c = 0; c < 4; c++) {
            float s = sv[c];
            if (s > SCORE_T) {
                unsigned k = __float_as_uint(s);
                if (k >= Kt) {
                    int p = atomicAdd(&sh_cnt, 1);
                    unsigned n = (unsigned)(n4 * 4 + c);
                    if (p < 2048)
                        arr[p] = ((unsigned long long)k << 32) |
                                 (unsigned long long)(0xFFFFFFFFu - n);
                }
            }
        }
    }
    __syncthreads();

    // ---- phase 3: bitonic sort 2048 desc (score desc, idx asc on ties) ----
    for (int k = 2; k <= 2048; k <<= 1)
        for (int j = k >> 1; j > 0; j >>= 1) {
            __syncthreads();
            for (int i = tid; i < 2048; i += 1024) {
                int ixj = i ^ j;
                if (ixj > i) {
                    unsigned long long a = arr[i], b = arr[ixj];
                    if (((i & k) == 0) ? (a < b) : (a > b)) { arr[i] = b; arr[ixj] = a; }
                }
            }
        }
    __syncthreads();

    // ---- epilogue: write topval + decode box inline ----
    if (tid < KK) {
        unsigned long long v = arr[tid];
        float val;
        int idx;
        if (v) {
            val = __uint_as_float((unsigned)(v >> 32));
            idx = (int)(0xFFFFFFFFu - (unsigned)v);
        } else {
            val = -1.0f;    // padding; cannot surface in output
            idx = tid;
        }
        g_topval[bc * KK + tid] = val;
        int b = bc / CC;
        float4 an = anchors[idx];
        float4 dl = deltas[(size_t)b * NN + idx];
        float acx = (an.x + an.z) * 0.5f, acy = (an.y + an.w) * 0.5f;
        float aw = fmaxf(an.z - an.x, 1.0f), ah = fmaxf(an.w - an.y, 1.0f);
        float cx = dl.x * aw + acx, cy = dl.y * ah + acy;
        float w = expf(fminf(dl.z, 4.0f)) * aw;
        float h = expf(fminf(dl.w, 4.0f)) * ah;
        g_topbox[bc * KK + tid] = make_float4(cx - w * 0.5f, cy - h * 0.5f,
                                              cx + w * 0.5f, cy + h * 0.5f);
    }
}

// ---------------- K3: NMS suppression bitmatrix (row-pair per warp, u32 words) ----------------
__global__ __launch_bounds__(1024) void nms_mask_kernel() {
    int bc = blockIdx.x;
    int tid = threadIdx.x;
    int lane = tid & 31;
    int wid = tid >> 5;
    __shared__ float4 sb[KK];
    __shared__ float sa[KK];
    for (int i = tid; i < KK; i += 1024) {
        float4 bx = g_topbox[bc * KK + i];
        sb[i] = bx;
        sa[i] = (bx.z - bx.x) * (bx.w - bx.y);
    }
    __syncthreads();
    int gw = blockIdx.y * 32 + wid;   // 0..127 global warp within bc
    for (int p = gw; p < KK / 2; p += 128) {
        int i0 = p * 2, i1 = i0 + 1;
        float4 bA = sb[i0], bB = sb[i1];
        float aA = sa[i0], aB = sa[i1];
        unsigned* r0 = &g_mask32[((size_t)bc * KK + i0) * 32];
        unsigned* r1 = r0 + 32;
        for (int w = i0 >> 5; w < 32; w++) {
            int j = (w << 5) + lane;
            bool sA = false, sB = false;
            if (j < KK) {
                float4 bj = sb[j];
                float aj = sa[j];
                float x1a = fmaxf(bA.x, bj.x), y1a = fmaxf(bA.y, bj.y);
                float x2a = fminf(bA.z, bj.z), y2a = fminf(bA.w, bj.w);
                float ia = fmaxf(x2a - x1a, 0.0f) * fmaxf(y2a - y1a, 0.0f);
                sA = (j > i0) && (ia > 0.5f * fmaxf(aA + aj - ia, 1e-6f));
                float x1b = fmaxf(bB.x, bj.x), y1b = fmaxf(bB.y, bj.y);
                float x2b = fminf(bB.z, bj.z), y2b = fminf(bB.w, bj.w);
                float ib = fmaxf(x2b - x1b, 0.0f) * fmaxf(y2b - y1b, 0.0f);
                sB = (j > i1) && (ib > 0.5f * fmaxf(aB + aj - ib, 1e-6f));
            }
            unsigned balA = __ballot_sync(0xFFFFFFFFu, sA);
            unsigned balB = __ballot_sync(0xFFFFFFFFu, sB);
            if (lane == 0) { r0[w] = balA; r1[w] = balB; }
        }
    }
}

// ---------------- K4: greedy reduction, 32x32 chunk solve + cp.async staging ----------------
__device__ __forceinline__ void cp_async16(unsigned saddr, const void* gaddr) {
    asm volatile("cp.async.cg.shared.global [%0], [%1], 16;" :: "r"(saddr), "l"(gaddr));
}
__device__ __forceinline__ void cp_commit() { asm volatile("cp.async.commit_group;"); }
__device__ __forceinline__ void cp_wait1() { asm volatile("cp.async.wait_group 1;"); }

__global__ __launch_bounds__(32) void nms_reduce_kernel() {
    int bc = blockIdx.x;
    int lane = threadIdx.x;
    const unsigned* m32 = g_mask32 + (size_t)bc * KK * 32;
    __shared__ __align__(16) unsigned stage[2][1024];   // 8 KB double buffer

    unsigned sbase0 = (unsigned)__cvta_generic_to_shared(&stage[0][0]);
    unsigned sbase1 = (unsigned)__cvta_generic_to_shared(&stage[1][0]);

    // issue chunk c into the given stage buffer.
    // chunk = nrows rows x 128 B/row; per lane: nrows*128/(32*16) = nrows/4 ops of 16 B.
    auto issue = [&](int c, unsigned sbase) {
        int nrows = min(32, KK - c * 32);
        int nops = nrows / 4;
        const char* g = (const char*)(m32 + (size_t)c * 1024);
        for (int k = 0; k < nops; k++) {
            int off = (k * 32 + lane) * 16;
            cp_async16(sbase + off, g + off);
        }
    };

    issue(0, sbase0);
    cp_commit();

    unsigned removed = 0u;
    unsigned keepbits = 0u;
    for (int c = 0; c < 32; c++) {
        if (c < 31) issue(c + 1, (c & 1) ? sbase0 : sbase1);
        cp_commit();
        cp_wait1();
        __syncwarp();
        const unsigned* st = stage[c & 1];
        int nr = (c == 31) ? 8 : 32;
        unsigned w[32];
#pragma unroll
        for (int s = 0; s < 32; s++) w[s] = (s < nr) ? st[s * 32 + lane] : 0u;
        // resolve greedy within chunk (lane c's column is the diagonal)
        unsigned kb = ~removed;
        if (c == 31) kb &= 0xFFu;
#pragma unroll
        for (int s = 0; s < 32; s++) {
            unsigned m = (unsigned)(-(int)((kb >> s) & 1u));
            kb &= ~(w[s] & m);
        }
        kb = __shfl_sync(0xFFFFFFFFu, kb, c);
        // apply kept rows' suppression (4-way OR trees)
        unsigned a0 = 0, a1 = 0, a2 = 0, a3 = 0;
#pragma unroll
        for (int s = 0; s < 32; s += 4) {
            a0 |= w[s + 0] & (unsigned)(-(int)((kb >> (s + 0)) & 1u));
            a1 |= w[s + 1] & (unsigned)(-(int)((kb >> (s + 1)) & 1u));
            a2 |= w[s + 2] & (unsigned)(-(int)((kb >> (s + 2)) & 1u));
            a3 |= w[s + 3] & (unsigned)(-(int)((kb >> (s + 3)) & 1u));
        }
        removed |= (a0 | a1) | (a2 | a3);
        if (lane == c) keepbits = kb;
        __syncwarp();
    }

    // ---- parallel epilogue: apply score threshold, write g_val, compact survivors ----
    int cnt = 0;
    for (int w = 0; w < 32; w++) {
        unsigned kb = __shfl_sync(0xFFFFFFFFu, keepbits, w);
        int i = w * 32 + lane;
        float v = (i < KK) ? g_topval[bc * KK + i] : -1.0f;
        bool valid = (i < KK) && ((kb >> lane) & 1u) && (v > SCORE_T);
        if (i < KK) g_val[bc * KK + i] = valid ? v : 0.0f;
        unsigned bal = __ballot_sync(0xFFFFFFFFu, valid);
        int pos = cnt + __popc(bal & ((1u << lane) - 1u));
        if (valid) {
            g_cval[bc * KK + pos] = v;      // survivors stay score-descending
            g_cidx[bc * KK + pos] = i;
        }
        cnt += __popc(bal);
    }
    if (lane == 0) g_cnt[bc] = cnt;
}

// ---------------- K5: per-image top-100 over 9 classes ----------------
__global__ __launch_bounds__(512) void final_kernel(float* __restrict__ out) {
    int b = blockIdx.x;
    int tid = threadIdx.x;
    __shared__ unsigned long long arr[1024];
    for (int i = tid; i < 1024; i += 512) arr[i] = 0ull;
    __syncthreads();
    // only the top-100 of each class can reach the global top-100
    for (int s = tid; s < 900; s += 512) {
        int c = s / 100, r = s % 100;
        int bc = b * 9 + c;
        if (r < g_cnt[bc]) {
            float v = g_cval[bc * KK + r];
            int k = g_cidx[bc * KK + r];
            unsigned flat = (unsigned)(c * KK + k);
            arr[s] = ((unsigned long long)__float_as_uint(v) << 32) |
                     (unsigned long long)(0xFFFFFFFFu - flat);
        }
    }
    __syncthreads();
    for (int k = 2; k <= 1024; k <<= 1)
        for (int j = k >> 1; j > 0; j >>= 1) {
            __syncthreads();
            for (int i = tid; i < 1024; i += 512) {
                int ixj = i ^ j;
                if (ixj > i) {
                    unsigned long long a = arr[i], bv = arr[ixj];
                    if (((i & k) == 0) ? (a < bv) : (a > bv)) { arr[i] = bv; arr[ixj] = a; }
                }
            }
        }
    __syncthreads();

    float* o = out + (size_t)b * MAXDET * 6;
    if (tid < MAXDET) {
        unsigned long long v = arr[tid];
        if (v) {
            unsigned flat = 0xFFFFFFFFu - (unsigned)v;
            int c = flat / KK, k2 = flat % KK;
            float4 bx = g_topbox[(b * 9 + c) * KK + k2];
            float scv = __uint_as_float((unsigned)(v >> 32));
            o[tid * 6 + 0] = bx.x; o[tid * 6 + 1] = bx.y;
            o[tid * 6 + 2] = bx.z; o[tid * 6 + 3] = bx.w;
            o[tid * 6 + 4] = scv;  o[tid * 6 + 5] = (float)c;
        }
    }
    __syncthreads();
    // exact-tie fallback: < 100 positive detections -> zero-score entries by ascending flat idx
    if (tid == 0 && arr[MAXDET - 1] == 0ull) {
        int f = 0;
        for (int t = 0; t < MAXDET; t++) {
            if (arr[t]) continue;
            while (f < 9000 && g_val[(size_t)b * 9000 + f] != 0.0f) f++;
            int c = 0, k2 = 0;
            float4 bx = make_float4(0.f, 0.f, 0.f, 0.f);
            if (f < 9000) {
                c = f / KK; k2 = f % KK;
                bx = g_topbox[(b * 9 + c) * KK + k2];
                f++;
            }
            o[t * 6 + 0] = bx.x; o[t * 6 + 1] = bx.y;
            o[t * 6 + 2] = bx.z; o[t * 6 + 3] = bx.w;
            o[t * 6 + 4] = 0.0f; o[t * 6 + 5] = (float)c;
        }
    }
}

// ---------------- launch ----------------
extern "C" void kernel_launch(void* const* d_in, const int* in_sizes, int n_in,
                              void* d_out, int out_size) {
    (void)in_sizes; (void)n_in; (void)out_size;
    const float* anchors = (const float*)d_in[0];
    const float* deltas  = (const float*)d_in[1];
    const float* cls     = (const float*)d_in[2];
    const float* obj     = (const float*)d_in[3];
    float* out = (float*)d_out;

    score_kernel<<<dim3(NN / 256, BB), 256>>>(cls, obj);
    select_kernel<<<BC, 1024>>>((const float4*)anchors, (const float4*)deltas);
    nms_mask_kernel<<<dim3(BC, 4), 1024>>>();
    nms_reduce_kernel<<<BC, 32>>>();
    final_kernel<<<BB, 512>>>(out);
}

// round 12
// speedup vs baseline: 1.3309x; 1.3174x over previous
#include <cuda_runtime.h>
#include <cuda_bf16.h>
#include <cstdint>

#define NN 193536
#define BB 16
#define CC 9
#define KK 1000
#define BC 144            // BB*CC
#define MAXDET 100
#define SCORE_T 0.05f
#define IOU_T 0.5f

// keys are positive floats in (0.05, 1): 20-bit prefixes span [0x3D4CC, 0x3F7FF]
#define P_LO 0x3D4CCu
#define HB 9012
#define HBPAD 9024        // padded to 282*32
#define KT_MIN 0x3D4CCCCEu   // smallest uint key with float > 0.05f

// ---------------- scratch (static device globals; no dynamic alloc) ----------------
__device__ float    g_scores[(size_t)BC * NN];       // ~111.5 MB, [(b*9+c)][n]
__device__ float    g_topval[BC * KK];
__device__ float4   g_topbox[BC * KK];
__device__ unsigned g_mask32[(size_t)BC * KK * 32];  // 18.4 MB suppression bitmatrix (u32 words)
__device__ float    g_val[BC * KK];                  // post-NMS score (0 for invalid)
__device__ float    g_cval[BC * KK];                 // compacted survivors (desc order)
__device__ int      g_cidx[BC * KK];
__device__ int      g_cnt[BC];

// ---------------- K1: sigmoid + transpose scores to class-major ----------------
__global__ __launch_bounds__(256) void score_kernel(const float* __restrict__ cls,
                                                    const float* __restrict__ obj) {
    int b = blockIdx.y;
    int n0 = blockIdx.x * 256;
    int tid = threadIdx.x;
    __shared__ float sh[256 * 9];
    const float* src = cls + ((size_t)b * NN + n0) * 9;
    for (int i = tid; i < 2304; i += 256) sh[i] = src[i];
    __syncthreads();
    int n = n0 + tid;
    float so = 1.0f / (1.0f + expf(-obj[(size_t)b * NN + n]));
#pragma unroll
    for (int c = 0; c < 9; c++) {
        float s = 1.0f / (1.0f + expf(-sh[tid * 9 + c]));
        g_scores[((size_t)(b * 9 + c)) * NN + n] = s * so;
    }
}

// ---------------- scan helper: boundary bin from top, given remaining need ----------------
__device__ __forceinline__ void scan_boundary(unsigned* hist, unsigned* gsum, int NG,
                                              int tid, int* sh_sel, int* sh_need,
                                              int* sh_take, unsigned* sh_gat) {
    if (tid < NG) {
        unsigned t = 0;
        int base = tid * 32;
#pragma unroll 8
        for (int i = 0; i < 32; i++) t += hist[base + i];
        gsum[tid] = t;
    }
    __syncthreads();
    if (tid == 0) {
        int need = *sh_need;
        unsigned acc = 0;
        int g = NG - 1;
        for (; g >= 0; g--) {
            if (acc + gsum[g] >= (unsigned)need) break;
            acc += gsum[g];
        }
        if (g < 0) {
            *sh_take = 1;  // fewer than `need` candidates total
        } else {
            int bin = g * 32 + 31;
            for (;; bin--) {
                if (acc + hist[bin] >= (unsigned)need) break;
                acc += hist[bin];
            }
            *sh_sel = bin;
            *sh_need = need - (int)acc;          // remaining need inside boundary bin
            *sh_gat = acc + hist[bin];           // total items with key >= bin prefix
        }
    }
    __syncthreads();
}

// ---------------- K2: per-(b,c) exact top-1000, SINGLE g_scores pass + decode ----------------
__global__ __launch_bounds__(1024) void select_kernel(const float4* __restrict__ anchors,
                                                      const float4* __restrict__ deltas) {
    int bc = blockIdx.x;
    int tid = threadIdx.x;
    const float* sc = g_scores + (size_t)bc * NN;
    const float4* sc4 = (const float4*)sc;

    __shared__ __align__(16) unsigned char sraw[HBPAD * 4];   // 36 KB overlay
    unsigned* hist = (unsigned*)sraw;                         // fallback hists
    unsigned* samp = (unsigned*)sraw;                         // 16 KB sample buffer
    unsigned long long* arr = (unsigned long long*)sraw;      // 32 KB gather/sort buffer
    __shared__ unsigned gsum[288];
    __shared__ int sh_sel, sh_need, sh_take, sh_cnt;
    __shared__ unsigned sh_gat, sh_T;

    // ---- phase 0: sample 4096 values, sort desc, T = 48th largest ----
    // expected population count >= T: 48 * 47.25 = 2268, sigma ~327
    // -> P(count > 4096) ~ 2e-8, P(count < 1000) ~ 5e-5 per instance (fallback covers)
    for (int i = tid; i < 4096; i += 1024) {
        float s = sc[i * 47];                  // 47*4095 = 192465 < NN
        samp[i] = (s > SCORE_T) ? __float_as_uint(s) : 0u;
    }
    __syncthreads();
    for (int k = 2; k <= 4096; k <<= 1)
        for (int j = k >> 1; j > 0; j >>= 1) {
            __syncthreads();
            for (int i = tid; i < 4096; i += 1024) {
                int ixj = i ^ j;
                if (ixj > i) {
                    unsigned a = samp[i], b = samp[ixj];
                    if (((i & k) == 0) ? (a < b) : (a > b)) { samp[i] = b; samp[ixj] = a; }
                }
            }
        }
    __syncthreads();
    if (tid == 0) {
        unsigned t = samp[47];
        sh_T = (t >= KT_MIN) ? t : KT_MIN;
    }
    __syncthreads();
    unsigned T = sh_T;
    __syncthreads();

    // ---- phase 1: single-pass gather of keys >= T into 4096-slot buffer ----
    for (int i = tid; i < 4096; i += 1024) arr[i] = 0ull;
    if (tid == 0) sh_cnt = 0;
    __syncthreads();
    for (int n4 = tid; n4 < NN / 4; n4 += 1024) {
        float4 v = sc4[n4];
        float sv[4] = {v.x, v.y, v.z, v.w};
#pragma unroll
        for (int c = 0; c < 4; c++) {
            float s = sv[c];
            if (s > SCORE_T) {
                unsigned k = __float_as_uint(s);
                if (k >= T) {
                    int p = atomicAdd(&sh_cnt, 1);
                    unsigned n = (unsigned)(n4 * 4 + c);
                    if (p < 4096)
                        arr[p] = ((unsigned long long)k << 32) |
                                 (unsigned long long)(0xFFFFFFFFu - n);
                }
            }
        }
    }
    __syncthreads();
    int cnt = sh_cnt;
    bool fast = (cnt <= 4096) && (cnt >= KK || T == KT_MIN);

    if (!fast) {
        // ---- exact fallback (cold): full two-pass radix-select over g_scores ----
        __syncthreads();
        for (int i = tid; i < HBPAD; i += 1024) hist[i] = 0;
        if (tid == 0) { sh_need = KK; sh_take = 0; }
        __syncthreads();
        for (int n4 = tid; n4 < NN / 4; n4 += 1024) {
            float4 v = sc4[n4];
            float sv[4] = {v.x, v.y, v.z, v.w};
#pragma unroll
            for (int c = 0; c < 4; c++) {
                float s = sv[c];
                if (s > SCORE_T) {
                    int bin = (int)(__float_as_uint(s) >> 12) - (int)P_LO;
                    bin = min(max(bin, 0), HB - 1);
                    atomicAdd(&hist[bin], 1u);
                }
            }
        }
        __syncthreads();
        scan_boundary(hist, gsum, 282, tid, &sh_sel, &sh_need, &sh_take, &sh_gat);
        unsigned Kt;
        if (sh_take) {
            Kt = KT_MIN;
        } else {
            unsigned prefix = P_LO + (unsigned)sh_sel;
            Kt = prefix << 12;
            if (sh_gat > 4096u) {
                __syncthreads();
                for (int i = tid; i < 4096; i += 1024) hist[i] = 0;
                __syncthreads();
                for (int n4 = tid; n4 < NN / 4; n4 += 1024) {
                    float4 v = sc4[n4];
                    float sv[4] = {v.x, v.y, v.z, v.w};
#pragma unroll
                    for (int c = 0; c < 4; c++) {
                        float s = sv[c];
                        if (s > SCORE_T) {
                            unsigned k = __float_as_uint(s);
                            if ((k >> 12) == prefix) atomicAdd(&hist[k & 0xFFF], 1u);
                        }
                    }
                }
                __syncthreads();
                scan_boundary(hist, gsum, 128, tid, &sh_sel, &sh_need, &sh_take, &sh_gat);
                Kt = (prefix << 12) | (unsigned)sh_sel;
            }
        }
        __syncthreads();
        for (int i = tid; i < 4096; i += 1024) arr[i] = 0ull;
        if (tid == 0) sh_cnt = 0;
        __syncthreads();
        for (int n4 = tid; n4 < NN / 4; n4 += 1024) {
            float4 v = sc4[n4];
            float sv[4] = {v.x, v.y, v.z, v.w};
#pragma unroll
            for (int c = 0; c < 4; c++) {
                float s = sv[c];
                if (s > SCORE_T) {
                    unsigned k = __float_as_uint(s);
                    if (k >= Kt) {
                        int p = atomicAdd(&sh_cnt, 1);
                        unsigned n = (unsigned)(n4 * 4 + c);
                        if (p < 4096)
                            arr[p] = ((unsigned long long)k << 32) |
                                     (unsigned long long)(0xFFFFFFFFu - n);
                    }
                }
            }
        }
        __syncthreads();
    }

    // ---- phase 2: bitonic sort 4096 desc (score desc, idx asc on ties) ----
    for (int k = 2; k <= 4096; k <<= 1)
        for (int j = k >> 1; j > 0; j >>= 1) {
            __syncthreads();
            for (int i = tid; i < 4096; i += 1024) {
                int ixj = i ^ j;
                if (ixj > i) {
                    unsigned long long a = arr[i], b = arr[ixj];
                    if (((i & k) == 0) ? (a < b) : (a > b)) { arr[i] = b; arr[ixj] = a; }
                }
            }
        }
    __syncthreads();

    // ---- epilogue: write topval + decode box inline ----
    if (tid < KK) {
        unsigned long long v = arr[tid];
        float val;
        int idx;
        if (v) {
            val = __uint_as_float((unsigned)(v >> 32));
            idx = (int)(0xFFFFFFFFu - (unsigned)v);
        } else {
            val = -1.0f;    // padding; cannot surface in output
            idx = tid;
        }
        g_topval[bc * KK + tid] = val;
        int b = bc / CC;
        float4 an = anchors[idx];
        float4 dl = deltas[(size_t)b * NN + idx];
        float acx = (an.x + an.z) * 0.5f, acy = (an.y + an.w) * 0.5f;
        float aw = fmaxf(an.z - an.x, 1.0f), ah = fmaxf(an.w - an.y, 1.0f);
        float cx = dl.x * aw + acx, cy = dl.y * ah + acy;
        float w = expf(fminf(dl.z, 4.0f)) * aw;
        float h = expf(fminf(dl.w, 4.0f)) * ah;
        g_topbox[bc * KK + tid] = make_float4(cx - w * 0.5f, cy - h * 0.5f,
                                              cx + w * 0.5f, cy + h * 0.5f);
    }
}

// ---------------- K3: NMS suppression bitmatrix (4 rows/warp, balanced quads) ----------------
__device__ __forceinline__ bool iou_sup(float4 bi, float ai, float4 bj, float aj, bool after) {
    float x1 = fmaxf(bi.x, bj.x), y1 = fmaxf(bi.y, bj.y);
    float x2 = fminf(bi.z, bj.z), y2 = fminf(bi.w, bj.w);
    float inter = fmaxf(x2 - x1, 0.0f) * fmaxf(y2 - y1, 0.0f);
    return after && (inter > 0.5f * fmaxf(ai + aj - inter, 1e-6f));
}

__global__ __launch_bounds__(1024) void nms_mask_kernel() {
    int bc = blockIdx.x;
    int tid = threadIdx.x;
    int lane = tid & 31;
    int wid = tid >> 5;
    __shared__ float4 sb[1024];          // padded: rows 1000..1023 are zero boxes
    __shared__ float sa[1024];
    {
        int i = tid;
        float4 bx = (i < KK) ? g_topbox[bc * KK + i] : make_float4(0.f, 0.f, 0.f, 0.f);
        sb[i] = bx;
        sa[i] = (bx.z - bx.x) * (bx.w - bx.y);
    }
    __syncthreads();
    int gw = blockIdx.y * 32 + wid;      // 0..127 global warp within bc
    if (gw >= 125) return;               // 125 quad-pairs cover all 250 quads
#pragma unroll 1
    for (int t = 0; t < 2; t++) {
        int q = t ? (249 - gw) : gw;     // triangle-balanced pairing (~33 words/warp)
        int i0 = q * 4;
        float4 b0 = sb[i0 + 0], b1 = sb[i0 + 1], b2 = sb[i0 + 2], b3 = sb[i0 + 3];
        float a0 = sa[i0 + 0], a1 = sa[i0 + 1], a2 = sa[i0 + 2], a3 = sa[i0 + 3];
        unsigned* r = &g_mask32[((size_t)bc * KK + i0) * 32];
        for (int w = i0 >> 5; w < 32; w++) {
            int j = (w << 5) + lane;
            float4 bj = sb[j];
            float aj = sa[j];
            bool c0 = iou_sup(b0, a0, bj, aj, j > i0);
            bool c1 = iou_sup(b1, a1, bj, aj, j > i0 + 1);
            bool c2 = iou_sup(b2, a2, bj, aj, j > i0 + 2);
            bool c3 = iou_sup(b3, a3, bj, aj, j > i0 + 3);
            unsigned s0 = __ballot_sync(0xFFFFFFFFu, c0);
            unsigned s1 = __ballot_sync(0xFFFFFFFFu, c1);
            unsigned s2 = __ballot_sync(0xFFFFFFFFu, c2);
            unsigned s3 = __ballot_sync(0xFFFFFFFFu, c3);
            if (lane == 0) {
                r[w] = s0; r[w + 32] = s1; r[w + 64] = s2; r[w + 96] = s3;
            }
        }
    }
}

// ---------------- K4: greedy reduction, 32x32 chunk solve + cp.async staging ----------------
__device__ __forceinline__ void cp_async16(unsigned saddr, const void* gaddr) {
    asm volatile("cp.async.cg.shared.global [%0], [%1], 16;" :: "r"(saddr), "l"(gaddr));
}
__device__ __forceinline__ void cp_commit() { asm volatile("cp.async.commit_group;"); }
__device__ __forceinline__ void cp_wait1() { asm volatile("cp.async.wait_group 1;"); }

__global__ __launch_bounds__(32) void nms_reduce_kernel() {
    int bc = blockIdx.x;
    int lane = threadIdx.x;
    const unsigned* m32 = g_mask32 + (size_t)bc * KK * 32;
    __shared__ __align__(16) unsigned stage[2][1024];   // 8 KB double buffer

    unsigned sbase0 = (unsigned)__cvta_generic_to_shared(&stage[0][0]);
    unsigned sbase1 = (unsigned)__cvta_generic_to_shared(&stage[1][0]);

    // issue chunk c: nrows rows x 128 B/row; per lane nrows/4 ops of 16 B.
    auto issue = [&](int c, unsigned sbase) {
        int nrows = min(32, KK - c * 32);
        int nops = nrows / 4;
        const char* g = (const char*)(m32 + (size_t)c * 1024);
        for (int k = 0; k < nops; k++) {
            int off = (k * 32 + lane) * 16;
            cp_async16(sbase + off, g + off);
        }
    };

    issue(0, sbase0);
    cp_commit();

    unsigned removed = 0u;
    unsigned keepbits = 0u;
    for (int c = 0; c < 32; c++) {
        if (c < 31) issue(c + 1, (c & 1) ? sbase0 : sbase1);
        cp_commit();
        cp_wait1();
        __syncwarp();
        const unsigned* st = stage[c & 1];
        int nr = (c == 31) ? 8 : 32;
        unsigned w[32];
#pragma unroll
        for (int s = 0; s < 32; s++) w[s] = (s < nr) ? st[s * 32 + lane] : 0u;
        // resolve greedy within chunk (lane c's column is the diagonal)
        unsigned kb = ~removed;
        if (c == 31) kb &= 0xFFu;
#pragma unroll
        for (int s = 0; s < 32; s++) {
            unsigned m = (unsigned)(-(int)((kb >> s) & 1u));
            kb &= ~(w[s] & m);
        }
        kb = __shfl_sync(0xFFFFFFFFu, kb, c);
        // apply kept rows' suppression (4-way OR trees)
        unsigned a0 = 0, a1 = 0, a2 = 0, a3 = 0;
#pragma unroll
        for (int s = 0; s < 32; s += 4) {
            a0 |= w[s + 0] & (unsigned)(-(int)((kb >> (s + 0)) & 1u));
            a1 |= w[s + 1] & (unsigned)(-(int)((kb >> (s + 1)) & 1u));
            a2 |= w[s + 2] & (unsigned)(-(int)((kb >> (s + 2)) & 1u));
            a3 |= w[s + 3] & (unsigned)(-(int)((kb >> (s + 3)) & 1u));
        }
        removed |= (a0 | a1) | (a2 | a3);
        if (lane == c) keepbits = kb;
        __syncwarp();
    }

    // ---- parallel epilogue: apply score threshold, write g_val, compact survivors ----
    int cnt = 0;
    for (int w = 0; w < 32; w++) {
        unsigned kb = __shfl_sync(0xFFFFFFFFu, keepbits, w);
        int i = w * 32 + lane;
        float v = (i < KK) ? g_topval[bc * KK + i] : -1.0f;
        bool valid = (i < KK) && ((kb >> lane) & 1u) && (v > SCORE_T);
        if (i < KK) g_val[bc * KK + i] = valid ? v : 0.0f;
        unsigned bal = __ballot_sync(0xFFFFFFFFu, valid);
        int pos = cnt + __popc(bal & ((1u << lane) - 1u));
        if (valid) {
            g_cval[bc * KK + pos] = v;      // survivors stay score-descending
            g_cidx[bc * KK + pos] = i;
        }
        cnt += __popc(bal);
    }
    if (lane == 0) g_cnt[bc] = cnt;
}

// ---------------- K5: per-image top-100 over 9 classes ----------------
__global__ __launch_bounds__(512) void final_kernel(float* __restrict__ out) {
    int b = blockIdx.x;
    int tid = threadIdx.x;
    __shared__ unsigned long long arr[1024];
    for (int i = tid; i < 1024; i += 512) arr[i] = 0ull;
    __syncthreads();
    // only the top-100 of each class can reach the global top-100
    for (int s = tid; s < 900; s += 512) {
        int c = s / 100, r = s % 100;
        int bc = b * 9 + c;
        if (r < g_cnt[bc]) {
            float v = g_cval[bc * KK + r];
            int k = g_cidx[bc * KK + r];
            unsigned flat = (unsigned)(c * KK + k);
            arr[s] = ((unsigned long long)__float_as_uint(v) << 32) |
                     (unsigned long long)(0xFFFFFFFFu - flat);
        }
    }
    __syncthreads();
    for (int k = 2; k <= 1024; k <<= 1)
        for (int j = k >> 1; j > 0; j >>= 1) {
            __syncthreads();
            for (int i = tid; i < 1024; i += 512) {
                int ixj = i ^ j;
                if (ixj > i) {
                    unsigned long long a = arr[i], bv = arr[ixj];
                    if (((i & k) == 0) ? (a < bv) : (a > bv)) { arr[i] = bv; arr[ixj] = a; }
                }
            }
        }
    __syncthreads();

    float* o = out + (size_t)b * MAXDET * 6;
    if (tid < MAXDET) {
        unsigned long long v = arr[tid];
        if (v) {
            unsigned flat = 0xFFFFFFFFu - (unsigned)v;
            int c = flat / KK, k2 = flat % KK;
            float4 bx = g_topbox[(b * 9 + c) * KK + k2];
            float scv = __uint_as_float((unsigned)(v >> 32));
            o[tid * 6 + 0] = bx.x; o[tid * 6 + 1] = bx.y;
            o[tid * 6 + 2] = bx.z; o[tid * 6 + 3] = bx.w;
            o[tid * 6 + 4] = scv;  o[tid * 6 + 5] = (float)c;
        }
    }
    __syncthreads();
    // exact-tie fallback: < 100 positive detections -> zero-score entries by ascending flat idx
    if (tid == 0 && arr[MAXDET - 1] == 0ull) {
        int f = 0;
        for (int t = 0; t < MAXDET; t++) {
            if (arr[t]) continue;
            while (f < 9000 && g_val[(size_t)b * 9000 + f] != 0.0f) f++;
            int c = 0, k2 = 0;
            float4 bx = make_float4(0.f, 0.f, 0.f, 0.f);
            if (f < 9000) {
                c = f / KK; k2 = f % KK;
                bx = g_topbox[(b * 9 + c) * KK + k2];
                f++;
            }
            o[t * 6 + 0] = bx.x; o[t * 6 + 1] = bx.y;
            o[t * 6 + 2] = bx.z; o[t * 6 + 3] = bx.w;
            o[t * 6 + 4] = 0.0f; o[t * 6 + 5] = (float)c;
        }
    }
}

// ---------------- launch ----------------
extern "C" void kernel_launch(void* const* d_in, const int* in_sizes, int n_in,
                              void* d_out, int out_size) {
    (void)in_sizes; (void)n_in; (void)out_size;
    const float* anchors = (const float*)d_in[0];
    const float* deltas  = (const float*)d_in[1];
    const float* cls     = (const float*)d_in[2];
    const float* obj     = (const float*)d_in[3];
    float* out = (float*)d_out;

    score_kernel<<<dim3(NN / 256, BB), 256>>>(cls, obj);
    select_kernel<<<BC, 1024>>>((const float4*)anchors, (const float4*)deltas);
    nms_mask_kernel<<<dim3(BC, 4), 1024>>>();
    nms_reduce_kernel<<<BC, 32>>>();
    final_kernel<<<BB, 512>>>(out);
}

// round 13
// speedup vs baseline: 1.4983x; 1.1258x over previous
#include <cuda_runtime.h>
#include <cuda_bf16.h>
#include <cstdint>

#define NN 193536
#define BB 16
#define CC 9
#define KK 1000
#define BC 144            // BB*CC
#define MAXDET 100
#define SCORE_T 0.05f
#define IOU_T 0.5f

// keys are positive floats in (0.05, 1): 20-bit prefixes span [0x3D4CC, 0x3F7FF]
#define P_LO 0x3D4CCu
#define HB 9012
#define HBPAD 9024        // padded to 282*32
#define KT_MIN 0x3D4CCCCEu   // smallest uint key with float > 0.05f

// ---------------- scratch (static device globals; no dynamic alloc) ----------------
__device__ float    g_scores[(size_t)BC * NN];       // ~111.5 MB, [(b*9+c)][n]
__device__ float    g_topval[BC * KK];
__device__ float4   g_topbox[BC * KK];
__device__ unsigned g_mask32[(size_t)BC * KK * 32];  // 18.4 MB suppression bitmatrix (u32 words)
__device__ float    g_val[BC * KK];                  // post-NMS score (0 for invalid)
__device__ float    g_cval[BC * KK];                 // compacted survivors (desc order)
__device__ int      g_cidx[BC * KK];
__device__ int      g_cnt[BC];

// ---------------- K1: sigmoid + transpose scores to class-major ----------------
__global__ __launch_bounds__(256) void score_kernel(const float* __restrict__ cls,
                                                    const float* __restrict__ obj) {
    int b = blockIdx.y;
    int n0 = blockIdx.x * 256;
    int tid = threadIdx.x;
    __shared__ float sh[256 * 9];
    const float* src = cls + ((size_t)b * NN + n0) * 9;
    for (int i = tid; i < 2304; i += 256) sh[i] = src[i];
    __syncthreads();
    int n = n0 + tid;
    float so = 1.0f / (1.0f + expf(-obj[(size_t)b * NN + n]));
#pragma unroll
    for (int c = 0; c < 9; c++) {
        float s = 1.0f / (1.0f + expf(-sh[tid * 9 + c]));
        g_scores[((size_t)(b * 9 + c)) * NN + n] = s * so;
    }
}

// ---------------- scan helper: boundary bin from top, given remaining need ----------------
__device__ __forceinline__ void scan_boundary(unsigned* hist, unsigned* gsum, int NG,
                                              int tid, int* sh_sel, int* sh_need,
                                              int* sh_take, unsigned* sh_gat) {
    if (tid < NG) {
        unsigned t = 0;
        int base = tid * 32;
#pragma unroll 8
        for (int i = 0; i < 32; i++) t += hist[base + i];
        gsum[tid] = t;
    }
    __syncthreads();
    if (tid == 0) {
        int need = *sh_need;
        unsigned acc = 0;
        int g = NG - 1;
        for (; g >= 0; g--) {
            if (acc + gsum[g] >= (unsigned)need) break;
            acc += gsum[g];
        }
        if (g < 0) {
            *sh_take = 1;  // fewer than `need` candidates total
        } else {
            int bin = g * 32 + 31;
            for (;; bin--) {
                if (acc + hist[bin] >= (unsigned)need) break;
                acc += hist[bin];
            }
            *sh_sel = bin;
            *sh_need = need - (int)acc;          // remaining need inside boundary bin
            *sh_gat = acc + hist[bin];           // total items with key >= bin prefix
        }
    }
    __syncthreads();
}

// ---------------- K2: per-(b,c) exact top-1000, SINGLE g_scores pass + decode ----------------
__global__ __launch_bounds__(1024) void select_kernel(const float4* __restrict__ anchors,
                                                      const float4* __restrict__ deltas) {
    int bc = blockIdx.x;
    int tid = threadIdx.x;
    const float* sc = g_scores + (size_t)bc * NN;
    const float4* sc4 = (const float4*)sc;

    __shared__ __align__(16) unsigned char sraw[HBPAD * 4];   // 36 KB overlay
    unsigned* hist = (unsigned*)sraw;                         // sample + fallback hists
    unsigned long long* arr = (unsigned long long*)sraw;      // 32 KB gather/sort buffer
    __shared__ unsigned gsum[288];
    __shared__ int sh_sel, sh_need, sh_take, sh_cnt;
    __shared__ unsigned sh_gat, sh_T;

    // ---- phase 0: histogram 4096 sampled keys, select 48th-largest bin floor as T ----
    // expected population count >= T: ~48 * 47.25 = 2268 (+ small bin overshoot), sigma ~340
    // -> P(count > 4096) ~ 1e-6, underflow (<1000) covered by exact fallback
    for (int i = tid; i < HBPAD; i += 1024) hist[i] = 0;
    if (tid == 0) { sh_need = 48; sh_take = 0; }
    __syncthreads();
    for (int i = tid; i < 4096; i += 1024) {
        float s = sc[i * 47];                  // 47*4095 = 192465 < NN
        if (s > SCORE_T) {
            int bin = (int)(__float_as_uint(s) >> 12) - (int)P_LO;
            bin = min(max(bin, 0), HB - 1);
            atomicAdd(&hist[bin], 1u);
        }
    }
    __syncthreads();
    scan_boundary(hist, gsum, 282, tid, &sh_sel, &sh_need, &sh_take, &sh_gat);
    if (tid == 0) {
        unsigned t = sh_take ? KT_MIN : ((P_LO + (unsigned)sh_sel) << 12);
        sh_T = (t >= KT_MIN) ? t : KT_MIN;
    }
    __syncthreads();
    unsigned T = sh_T;
    __syncthreads();

    // ---- phase 1: single-pass gather of keys >= T into 4096-slot buffer ----
    for (int i = tid; i < 4096; i += 1024) arr[i] = 0ull;
    if (tid == 0) sh_cnt = 0;
    __syncthreads();
    for (int n4 = tid; n4 < NN / 4; n4 += 1024) {
        float4 v = sc4[n4];
        float sv[4] = {v.x, v.y, v.z, v.w};
#pragma unroll
        for (int c = 0; c < 4; c++) {
            float s = sv[c];
            if (s > SCORE_T) {
                unsigned k = __float_as_uint(s);
                if (k >= T) {
                    int p = atomicAdd(&sh_cnt, 1);
                    unsigned n = (unsigned)(n4 * 4 + c);
                    if (p < 4096)
                        arr[p] = ((unsigned long long)k << 32) |
                                 (unsigned long long)(0xFFFFFFFFu - n);
                }
            }
        }
    }
    __syncthreads();
    int cnt = sh_cnt;
    bool fast = (cnt <= 4096) && (cnt >= KK || T == KT_MIN);

    if (!fast) {
        // ---- exact fallback (cold): full two-pass radix-select over g_scores ----
        __syncthreads();
        for (int i = tid; i < HBPAD; i += 1024) hist[i] = 0;
        if (tid == 0) { sh_need = KK; sh_take = 0; }
        __syncthreads();
        for (int n4 = tid; n4 < NN / 4; n4 += 1024) {
            float4 v = sc4[n4];
            float sv[4] = {v.x, v.y, v.z, v.w};
#pragma unroll
            for (int c = 0; c < 4; c++) {
                float s = sv[c];
                if (s > SCORE_T) {
                    int bin = (int)(__float_as_uint(s) >> 12) - (int)P_LO;
                    bin = min(max(bin, 0), HB - 1);
                    atomicAdd(&hist[bin], 1u);
                }
            }
        }
        __syncthreads();
        scan_boundary(hist, gsum, 282, tid, &sh_sel, &sh_need, &sh_take, &sh_gat);
        unsigned Kt;
        if (sh_take) {
            Kt = KT_MIN;
        } else {
            unsigned prefix = P_LO + (unsigned)sh_sel;
            Kt = prefix << 12;
            if (sh_gat > 4096u) {
                __syncthreads();
                for (int i = tid; i < 4096; i += 1024) hist[i] = 0;
                __syncthreads();
                for (int n4 = tid; n4 < NN / 4; n4 += 1024) {
                    float4 v = sc4[n4];
                    float sv[4] = {v.x, v.y, v.z, v.w};
#pragma unroll
                    for (int c = 0; c < 4; c++) {
                        float s = sv[c];
                        if (s > SCORE_T) {
                            unsigned k = __float_as_uint(s);
                            if ((k >> 12) == prefix) atomicAdd(&hist[k & 0xFFF], 1u);
                        }
                    }
                }
                __syncthreads();
                scan_boundary(hist, gsum, 128, tid, &sh_sel, &sh_need, &sh_take, &sh_gat);
                Kt = (prefix << 12) | (unsigned)sh_sel;
            }
        }
        __syncthreads();
        for (int i = tid; i < 4096; i += 1024) arr[i] = 0ull;
        if (tid == 0) sh_cnt = 0;
        __syncthreads();
        for (int n4 = tid; n4 < NN / 4; n4 += 1024) {
            float4 v = sc4[n4];
            float sv[4] = {v.x, v.y, v.z, v.w};
#pragma unroll
            for (int c = 0; c < 4; c++) {
                float s = sv[c];
                if (s > SCORE_T) {
                    unsigned k = __float_as_uint(s);
                    if (k >= Kt) {
                        int p = atomicAdd(&sh_cnt, 1);
                        unsigned n = (unsigned)(n4 * 4 + c);
                        if (p < 4096)
                            arr[p] = ((unsigned long long)k << 32) |
                                     (unsigned long long)(0xFFFFFFFFu - n);
                    }
                }
            }
        }
        __syncthreads();
    }

    // ---- phase 2: bitonic sort 4096 desc (score desc, idx asc on ties) ----
    for (int k = 2; k <= 4096; k <<= 1)
        for (int j = k >> 1; j > 0; j >>= 1) {
            __syncthreads();
            for (int i = tid; i < 4096; i += 1024) {
                int ixj = i ^ j;
                if (ixj > i) {
                    unsigned long long a = arr[i], b = arr[ixj];
                    if (((i & k) == 0) ? (a < b) : (a > b)) { arr[i] = b; arr[ixj] = a; }
                }
            }
        }
    __syncthreads();

    // ---- epilogue: write topval + decode box inline ----
    if (tid < KK) {
        unsigned long long v = arr[tid];
        float val;
        int idx;
        if (v) {
            val = __uint_as_float((unsigned)(v >> 32));
            idx = (int)(0xFFFFFFFFu - (unsigned)v);
        } else {
            val = -1.0f;    // padding; cannot surface in output
            idx = tid;
        }
        g_topval[bc * KK + tid] = val;
        int b = bc / CC;
        float4 an = anchors[idx];
        float4 dl = deltas[(size_t)b * NN + idx];
        float acx = (an.x + an.z) * 0.5f, acy = (an.y + an.w) * 0.5f;
        float aw = fmaxf(an.z - an.x, 1.0f), ah = fmaxf(an.w - an.y, 1.0f);
        float cx = dl.x * aw + acx, cy = dl.y * ah + acy;
        float w = expf(fminf(dl.z, 4.0f)) * aw;
        float h = expf(fminf(dl.w, 4.0f)) * ah;
        g_topbox[bc * KK + tid] = make_float4(cx - w * 0.5f, cy - h * 0.5f,
                                              cx + w * 0.5f, cy + h * 0.5f);
    }
}

// ---------------- K3: NMS suppression bitmatrix (4 rows/warp, 512-thr blocks) ----------------
__device__ __forceinline__ bool iou_sup(float4 bi, float ai, float4 bj, float aj, bool after) {
    float x1 = fmaxf(bi.x, bj.x), y1 = fmaxf(bi.y, bj.y);
    float x2 = fminf(bi.z, bj.z), y2 = fminf(bi.w, bj.w);
    float inter = fmaxf(x2 - x1, 0.0f) * fmaxf(y2 - y1, 0.0f);
    return after && (inter > 0.5f * fmaxf(ai + aj - inter, 1e-6f));
}

__global__ __launch_bounds__(512) void nms_mask_kernel() {
    int bc = blockIdx.x;
    int tid = threadIdx.x;
    int lane = tid & 31;
    int wid = tid >> 5;
    __shared__ float4 sb[1024];          // padded: rows 1000..1023 are zero boxes
    __shared__ float sa[1024];
    for (int i = tid; i < 1024; i += 512) {
        float4 bx = (i < KK) ? g_topbox[bc * KK + i] : make_float4(0.f, 0.f, 0.f, 0.f);
        sb[i] = bx;
        sa[i] = (bx.z - bx.x) * (bx.w - bx.y);
    }
    __syncthreads();
    int gw = blockIdx.y * 16 + wid;      // 0..127 global warp within bc
    if (gw >= 125) return;               // 125 quad-pairs cover all 250 quads
#pragma unroll 1
    for (int t = 0; t < 2; t++) {
        int q = t ? (249 - gw) : gw;     // triangle-balanced pairing (~33 words/warp)
        int i0 = q * 4;
        float4 b0 = sb[i0 + 0], b1 = sb[i0 + 1], b2 = sb[i0 + 2], b3 = sb[i0 + 3];
        float a0 = sa[i0 + 0], a1 = sa[i0 + 1], a2 = sa[i0 + 2], a3 = sa[i0 + 3];
        unsigned* r = &g_mask32[((size_t)bc * KK + i0) * 32];
        for (int w = i0 >> 5; w < 32; w++) {
            int j = (w << 5) + lane;
            float4 bj = sb[j];
            float aj = sa[j];
            bool c0 = iou_sup(b0, a0, bj, aj, j > i0);
            bool c1 = iou_sup(b1, a1, bj, aj, j > i0 + 1);
            bool c2 = iou_sup(b2, a2, bj, aj, j > i0 + 2);
            bool c3 = iou_sup(b3, a3, bj, aj, j > i0 + 3);
            unsigned s0 = __ballot_sync(0xFFFFFFFFu, c0);
            unsigned s1 = __ballot_sync(0xFFFFFFFFu, c1);
            unsigned s2 = __ballot_sync(0xFFFFFFFFu, c2);
            unsigned s3 = __ballot_sync(0xFFFFFFFFu, c3);
            if (lane == 0) {
                r[w] = s0; r[w + 32] = s1; r[w + 64] = s2; r[w + 96] = s3;
            }
        }
    }
}

// ---------------- K4: greedy reduction, 32x32 chunk solve + cp.async staging ----------------
__device__ __forceinline__ void cp_async16(unsigned saddr, const void* gaddr) {
    asm volatile("cp.async.cg.shared.global [%0], [%1], 16;" :: "r"(saddr), "l"(gaddr));
}
__device__ __forceinline__ void cp_commit() { asm volatile("cp.async.commit_group;"); }
__device__ __forceinline__ void cp_wait1() { asm volatile("cp.async.wait_group 1;"); }

__global__ __launch_bounds__(32) void nms_reduce_kernel() {
    int bc = blockIdx.x;
    int lane = threadIdx.x;
    const unsigned* m32 = g_mask32 + (size_t)bc * KK * 32;
    __shared__ __align__(16) unsigned stage[2][1024];   // 8 KB double buffer

    unsigned sbase0 = (unsigned)__cvta_generic_to_shared(&stage[0][0]);
    unsigned sbase1 = (unsigned)__cvta_generic_to_shared(&stage[1][0]);

    // issue chunk c: nrows rows x 128 B/row; per lane nrows/4 ops of 16 B.
    auto issue = [&](int c, unsigned sbase) {
        int nrows = min(32, KK - c * 32);
        int nops = nrows / 4;
        const char* g = (const char*)(m32 + (size_t)c * 1024);
        for (int k = 0; k < nops; k++) {
            int off = (k * 32 + lane) * 16;
            cp_async16(sbase + off, g + off);
        }
    };

    issue(0, sbase0);
    cp_commit();

    unsigned removed = 0u;
    unsigned keepbits = 0u;
    for (int c = 0; c < 32; c++) {
        if (c < 31) issue(c + 1, (c & 1) ? sbase0 : sbase1);
        cp_commit();
        cp_wait1();
        __syncwarp();
        const unsigned* st = stage[c & 1];
        int nr = (c == 31) ? 8 : 32;
        unsigned w[32];
#pragma unroll
        for (int s = 0; s < 32; s++) w[s] = (s < nr) ? st[s * 32 + lane] : 0u;
        // resolve greedy within chunk (lane c's column is the diagonal)
        unsigned kb = ~removed;
        if (c == 31) kb &= 0xFFu;
#pragma unroll
        for (int s = 0; s < 32; s++) {
            unsigned m = (unsigned)(-(int)((kb >> s) & 1u));
            kb &= ~(w[s] & m);
        }
        kb = __shfl_sync(0xFFFFFFFFu, kb, c);
        // apply kept rows' suppression (4-way OR trees)
        unsigned a0 = 0, a1 = 0, a2 = 0, a3 = 0;
#pragma unroll
        for (int s = 0; s < 32; s += 4) {
            a0 |= w[s + 0] & (unsigned)(-(int)((kb >> (s + 0)) & 1u));
            a1 |= w[s + 1] & (unsigned)(-(int)((kb >> (s + 1)) & 1u));
            a2 |= w[s + 2] & (unsigned)(-(int)((kb >> (s + 2)) & 1u));
            a3 |= w[s + 3] & (unsigned)(-(int)((kb >> (s + 3)) & 1u));
        }
        removed |= (a0 | a1) | (a2 | a3);
        if (lane == c) keepbits = kb;
        __syncwarp();
    }

    // ---- parallel epilogue: apply score threshold, write g_val, compact survivors ----
    int cnt = 0;
    for (int w = 0; w < 32; w++) {
        unsigned kb = __shfl_sync(0xFFFFFFFFu, keepbits, w);
        int i = w * 32 + lane;
        float v = (i < KK) ? g_topval[bc * KK + i] : -1.0f;
        bool valid = (i < KK) && ((kb >> lane) & 1u) && (v > SCORE_T);
        if (i < KK) g_val[bc * KK + i] = valid ? v : 0.0f;
        unsigned bal = __ballot_sync(0xFFFFFFFFu, valid);
        int pos = cnt + __popc(bal & ((1u << lane) - 1u));
        if (valid) {
            g_cval[bc * KK + pos] = v;      // survivors stay score-descending
            g_cidx[bc * KK + pos] = i;
        }
        cnt += __popc(bal);
    }
    if (lane == 0) g_cnt[bc] = cnt;
}

// ---------------- K5: per-image top-100 over 9 classes ----------------
__global__ __launch_bounds__(512) void final_kernel(float* __restrict__ out) {
    int b = blockIdx.x;
    int tid = threadIdx.x;
    __shared__ unsigned long long arr[1024];
    for (int i = tid; i < 1024; i += 512) arr[i] = 0ull;
    __syncthreads();
    // only the top-100 of each class can reach the global top-100
    for (int s = tid; s < 900; s += 512) {
        int c = s / 100, r = s % 100;
        int bc = b * 9 + c;
        if (r < g_cnt[bc]) {
            float v = g_cval[bc * KK + r];
            int k = g_cidx[bc * KK + r];
            unsigned flat = (unsigned)(c * KK + k);
            arr[s] = ((unsigned long long)__float_as_uint(v) << 32) |
                     (unsigned long long)(0xFFFFFFFFu - flat);
        }
    }
    __syncthreads();
    for (int k = 2; k <= 1024; k <<= 1)
        for (int j = k >> 1; j > 0; j >>= 1) {
            __syncthreads();
            for (int i = tid; i < 1024; i += 512) {
                int ixj = i ^ j;
                if (ixj > i) {
                    unsigned long long a = arr[i], bv = arr[ixj];
                    if (((i & k) == 0) ? (a < bv) : (a > bv)) { arr[i] = bv; arr[ixj] = a; }
                }
            }
        }
    __syncthreads();

    float* o = out + (size_t)b * MAXDET * 6;
    if (tid < MAXDET) {
        unsigned long long v = arr[tid];
        if (v) {
            unsigned flat = 0xFFFFFFFFu - (unsigned)v;
            int c = flat / KK, k2 = flat % KK;
            float4 bx = g_topbox[(b * 9 + c) * KK + k2];
            float scv = __uint_as_float((unsigned)(v >> 32));
            o[tid * 6 + 0] = bx.x; o[tid * 6 + 1] = bx.y;
            o[tid * 6 + 2] = bx.z; o[tid * 6 + 3] = bx.w;
            o[tid * 6 + 4] = scv;  o[tid * 6 + 5] = (float)c;
        }
    }
    __syncthreads();
    // exact-tie fallback: < 100 positive detections -> zero-score entries by ascending flat idx
    if (tid == 0 && arr[MAXDET - 1] == 0ull) {
        int f = 0;
        for (int t = 0; t < MAXDET; t++) {
            if (arr[t]) continue;
            while (f < 9000 && g_val[(size_t)b * 9000 + f] != 0.0f) f++;
            int c = 0, k2 = 0;
            float4 bx = make_float4(0.f, 0.f, 0.f, 0.f);
            if (f < 9000) {
                c = f / KK; k2 = f % KK;
                bx = g_topbox[(b * 9 + c) * KK + k2];
                f++;
            }
            o[t * 6 + 0] = bx.x; o[t * 6 + 1] = bx.y;
            o[t * 6 + 2] = bx.z; o[t * 6 + 3] = bx.w;
            o[t * 6 + 4] = 0.0f; o[t * 6 + 5] = (float)c;
        }
    }
}

// ---------------- launch ----------------
extern "C" void kernel_launch(void* const* d_in, const int* in_sizes, int n_in,
                              void* d_out, int out_size) {
    (void)in_sizes; (void)n_in; (void)out_size;
    const float* anchors = (const float*)d_in[0];
    const float* deltas  = (const float*)d_in[1];
    const float* cls     = (const float*)d_in[2];
    const float* obj     = (const float*)d_in[3];
    float* out = (float*)d_out;

    score_kernel<<<dim3(NN / 256, BB), 256>>>(cls, obj);
    select_kernel<<<BC, 1024>>>((const float4*)anchors, (const float4*)deltas);
    nms_mask_kernel<<<dim3(BC, 8), 512>>>();
    nms_reduce_kernel<<<BC, 32>>>();
    final_kernel<<<BB, 512>>>(out);
}